// round 5
// baseline (speedup 1.0000x reference)
#include <cuda_runtime.h>
#include <cstdint>

#define N_TOKENS 8192
#define IN_CH    4096
#define OUT_CH   4096
#define RANK     16
#define KC       128                  // k-chunk (floats) staged per pipeline stage
#define NCHUNK   (IN_CH / KC)         // 32
#define STAGES   4

typedef unsigned long long u64;

__device__ float g_t[N_TOKENS * RANK];   // t = x @ R^T

__device__ __forceinline__ u64 f2fma(u64 a, u64 b, u64 c) {
    u64 d;
    asm("fma.rn.f32x2 %0, %1, %2, %3;" : "=l"(d) : "l"(a), "l"(b), "l"(c));
    return d;
}
__device__ __forceinline__ u64 splat2(float v) {
    u64 d;
    asm("mov.b64 %0, {%1, %1};" : "=l"(d) : "f"(v));
    return d;
}
__device__ __forceinline__ u64 pack2(float lo, float hi) {
    u64 d;
    asm("mov.b64 %0, {%1, %2};" : "=l"(d) : "f"(lo), "f"(hi));
    return d;
}
__device__ __forceinline__ void cp_async16(uint32_t s, const void* g) {
    asm volatile("cp.async.cg.shared.global [%0], [%1], 16;" :: "r"(s), "l"(g));
}
__device__ __forceinline__ void cp_commit() {
    asm volatile("cp.async.commit_group;" ::: "memory");
}
__device__ __forceinline__ void cp_wait3() {
    asm volatile("cp.async.wait_group 3;" ::: "memory");
}

// ----------------------------------------------------------------------------
// Kernel 1: t[n, r] = sum_k x[n,k] * R[r,k]
// 256 thr = 8 warps = 2 token-groups x 4 rank-splits. Warp: 8 tokens x 4 ranks
// (acc = 32 u64). R staged through a 4-deep cp.async smem pipeline.
// Per-iteration order (fixes round-4 off-by-one):
//   sync (free buf c-1) -> stage c+3 + ALWAYS commit -> wait_group 3
//   (pending {c..c+3} -> chunk c retired) -> sync (visibility) -> compute c.
// ----------------------------------------------------------------------------
__global__ void __launch_bounds__(256)
k1_xRt(const float* __restrict__ x, const float* __restrict__ Rm) {
    __shared__ __align__(16) float Rs[STAGES][RANK][KC];   // 32 KB

    const int tid   = threadIdx.x;
    const int warp  = tid >> 5;
    const int lane  = tid & 31;
    const int tg    = warp >> 2;             // 0..1
    const int rs    = warp & 3;              // rank split: ranks rs*4 .. rs*4+3
    const int tok0  = blockIdx.x * 16 + tg * 8;
    const int rbase = rs * 4;

    const float* xr = x + (size_t)tok0 * IN_CH;

    // ---- prologue: stage chunks 0..2 (3 committed groups) ----
    uint32_t rs_base = (uint32_t)__cvta_generic_to_shared(&Rs[0][0][0]);
#pragma unroll
    for (int p = 0; p < STAGES - 1; p++) {
#pragma unroll
        for (int j = 0; j < 2; j++) {
            const int linear = tid + 256 * j;        // float4 idx in 16x128 tile
            const int row    = linear >> 5;          // 32 float4 per row
            const int colf   = (linear & 31) << 2;   // float offset
            cp_async16(rs_base + (uint32_t)(((p * RANK + row) * KC + colf) * 4),
                       &Rm[(size_t)row * IN_CH + p * KC + colf]);
        }
        cp_commit();
    }

    u64 acc[8][4];
#pragma unroll
    for (int t = 0; t < 8; t++)
#pragma unroll
        for (int r = 0; r < 4; r++) acc[t][r] = 0ull;

    // ---- x prefetch for chunk 0 ----
    uint4 xc[8], xn[8];
    {
        const int kf = lane * 4;
#pragma unroll
        for (int t = 0; t < 8; t++)
            xc[t] = __ldcs(reinterpret_cast<const uint4*>(&xr[(size_t)t * IN_CH + kf]));
    }

#pragma unroll 1
    for (int c = 0; c < NCHUNK; c++) {
        __syncthreads();       // all warps done computing chunk c-1 -> its buffer is free

        // stage chunk c+3 into buffer (c+3)%STAGES; ALWAYS commit (empty
        // groups at the tail keep wait_group accounting uniform)
        if (c + STAGES - 1 < NCHUNK) {
            const int pc = c + STAGES - 1;
            const int pb = pc & (STAGES - 1);
#pragma unroll
            for (int j = 0; j < 2; j++) {
                const int linear = tid + 256 * j;
                const int row    = linear >> 5;
                const int colf   = (linear & 31) << 2;
                cp_async16(rs_base + (uint32_t)(((pb * RANK + row) * KC + colf) * 4),
                           &Rm[(size_t)row * IN_CH + pc * KC + colf]);
            }
        }
        cp_commit();

        cp_wait3();            // pending {c..c+3}: guarantees chunk c retired
        __syncthreads();       // make chunk c's smem writes visible block-wide

        // x prefetch for chunk c+1
        if (c + 1 < NCHUNK) {
            const int kf = (c + 1) * KC + lane * 4;
#pragma unroll
            for (int t = 0; t < 8; t++)
                xn[t] = __ldcs(reinterpret_cast<const uint4*>(&xr[(size_t)t * IN_CH + kf]));
        }

        // compute chunk c
        const int buf = c & (STAGES - 1);
        const int ks  = lane * 4;
#pragma unroll
        for (int r = 0; r < 4; r++) {
            ulonglong2 rv = *reinterpret_cast<const ulonglong2*>(&Rs[buf][rbase + r][ks]);
#pragma unroll
            for (int t = 0; t < 8; t++) {
                const ulonglong2 xv = *reinterpret_cast<const ulonglong2*>(&xc[t]);
                acc[t][r] = f2fma(xv.x, rv.x, acc[t][r]);
                acc[t][r] = f2fma(xv.y, rv.y, acc[t][r]);
            }
        }
#pragma unroll
        for (int t = 0; t < 8; t++) xc[t] = xn[t];
    }

    // ---- reduce across lanes; lane 0 writes 4-rank slices ----
#pragma unroll
    for (int t = 0; t < 8; t++) {
        float s[4];
#pragma unroll
        for (int r = 0; r < 4; r++) {
            float2 v = *reinterpret_cast<float2*>(&acc[t][r]);
            s[r] = v.x + v.y;
        }
#pragma unroll
        for (int off = 16; off > 0; off >>= 1) {
#pragma unroll
            for (int r = 0; r < 4; r++)
                s[r] += __shfl_xor_sync(0xffffffffu, s[r], off);
        }
        if (lane == 0) {
            *reinterpret_cast<float4*>(g_t + (size_t)(tok0 + t) * RANK + rbase) =
                make_float4(s[0], s[1], s[2], s[3]);
        }
    }
}

// ----------------------------------------------------------------------------
// Kernel 2: out[n, o] = bias[o] + sum_r t[n,r] * L[o,r]
// 256 thr x 4 outputs each = 1024-output chunk; 32 tokens/block -> grid 1024.
// L transpose-packed in registers (32 u64); t splatted in smem, broadcast
// LDS.128; streaming STG.128.
// ----------------------------------------------------------------------------
__global__ void __launch_bounds__(256)
k2_tLt(const float* __restrict__ Lm, const float* __restrict__ bias,
       float* __restrict__ out) {
    __shared__ __align__(16) u64 ts2[32][16];    // 4 KB splatted t

    const int tid     = threadIdx.x;
    const int bo      = blockIdx.x & 3;          // 4 o-chunks of 1024
    const int bt      = blockIdx.x >> 2;         // 256 token tiles of 32
    const int tokbase = bt * 32;
    const int o4      = bo * 1024 + tid * 4;

    // L[o4..o4+3][0..15] -> f32x2 packed regs
    u64 Lp0[16], Lp1[16];
    {
        float4 v[4][4];
#pragma unroll
        for (int i = 0; i < 4; i++) {
            const float4* lr = reinterpret_cast<const float4*>(Lm + (size_t)(o4 + i) * RANK);
            v[i][0] = lr[0]; v[i][1] = lr[1]; v[i][2] = lr[2]; v[i][3] = lr[3];
        }
#pragma unroll
        for (int q = 0; q < 4; q++) {
            Lp0[q * 4 + 0] = pack2(v[0][q].x, v[1][q].x);
            Lp0[q * 4 + 1] = pack2(v[0][q].y, v[1][q].y);
            Lp0[q * 4 + 2] = pack2(v[0][q].z, v[1][q].z);
            Lp0[q * 4 + 3] = pack2(v[0][q].w, v[1][q].w);
            Lp1[q * 4 + 0] = pack2(v[2][q].x, v[3][q].x);
            Lp1[q * 4 + 1] = pack2(v[2][q].y, v[3][q].y);
            Lp1[q * 4 + 2] = pack2(v[2][q].z, v[3][q].z);
            Lp1[q * 4 + 3] = pack2(v[2][q].w, v[3][q].w);
        }
    }
    const ulonglong2 bv = *reinterpret_cast<const ulonglong2*>(&bias[o4]);

    // stage splatted t: 32 tokens x 16 ranks; threads 0..127, 4 per token
    if (tid < 128) {
        const int tok = tid >> 2;
        const int r0  = (tid & 3) * 4;
        float4 v = *reinterpret_cast<const float4*>(
            g_t + (size_t)(tokbase + tok) * RANK + r0);
        ts2[tok][r0 + 0] = splat2(v.x);
        ts2[tok][r0 + 1] = splat2(v.y);
        ts2[tok][r0 + 2] = splat2(v.z);
        ts2[tok][r0 + 3] = splat2(v.w);
    }
    __syncthreads();

    float* outp = out + (size_t)tokbase * OUT_CH + o4;
#pragma unroll 4
    for (int tok = 0; tok < 32; tok++) {
        const ulonglong2* tp2 = reinterpret_cast<const ulonglong2*>(ts2[tok]);
        u64 a0 = bv.x, a1 = bv.y;
#pragma unroll
        for (int h = 0; h < 8; h++) {
            ulonglong2 t2 = tp2[h];                 // broadcast LDS.128
            a0 = f2fma(t2.x, Lp0[h * 2 + 0], a0);
            a1 = f2fma(t2.x, Lp1[h * 2 + 0], a1);
            a0 = f2fma(t2.y, Lp0[h * 2 + 1], a0);
            a1 = f2fma(t2.y, Lp1[h * 2 + 1], a1);
        }
        ulonglong2 o;
        o.x = a0; o.y = a1;
        __stcs(reinterpret_cast<ulonglong2*>(outp + (size_t)tok * OUT_CH), o);
    }
}

extern "C" void kernel_launch(void* const* d_in, const int* in_sizes, int n_in,
                              void* d_out, int out_size) {
    (void)in_sizes; (void)n_in; (void)out_size;
    const float* x    = (const float*)d_in[0];   // [8192, 4096]
    const float* Lm   = (const float*)d_in[1];   // [4096, 16]
    const float* Rm   = (const float*)d_in[2];   // [16, 4096]
    const float* bias = (const float*)d_in[3];   // [4096]
    float* out = (float*)d_out;                  // [8192, 4096]

    k1_xRt<<<N_TOKENS / 16, 256>>>(x, Rm);
    k2_tLt<<<(N_TOKENS / 32) * (OUT_CH / 1024), 256>>>(Lm, bias, out);
}

// round 7
// speedup vs baseline: 1.4450x; 1.4450x over previous
#include <cuda_runtime.h>
#include <cstdint>

#define N_TOKENS 8192
#define IN_CH    4096
#define OUT_CH   4096
#define RANK     16

typedef unsigned long long u64;

__device__ float g_t[N_TOKENS * RANK];   // t = x @ R^T

__device__ __forceinline__ u64 f2fma(u64 a, u64 b, u64 c) {
    u64 d;
    asm("fma.rn.f32x2 %0, %1, %2, %3;" : "=l"(d) : "l"(a), "l"(b), "l"(c));
    return d;
}
__device__ __forceinline__ u64 splat2(float v) {
    u64 d;
    asm("mov.b64 %0, {%1, %1};" : "=l"(d) : "f"(v));
    return d;
}
__device__ __forceinline__ u64 pack2(float lo, float hi) {
    u64 d;
    asm("mov.b64 %0, {%1, %2};" : "=l"(d) : "f"(lo), "f"(hi));
    return d;
}

// ----------------------------------------------------------------------------
// Kernel 1: t[n, r] = sum_k x[n,k] * R[r,k]
// 128 thr = 4 warps = 2 token-groups x 2 rank-halves. Warp: 4 tokens x 8 ranks
// (acc = 32 u64). NO barriers, NO smem: x streamed via __ldcs (keeps L1 for R),
// R via plain LDG (8-row slice = 128 KB, L1-resident after first pass).
// Unroll-2 k-loop lets ptxas front-batch 8 x-LDG.128 -> deep MLP.
// ~115 regs -> 4 blocks/SM = 16 warps: in-flight x bytes ~16 KB/SM -> can
// sustain near-peak HBM read.
// ----------------------------------------------------------------------------
__global__ void __launch_bounds__(128)
k1_xRt(const float* __restrict__ x, const float* __restrict__ Rm) {
    const int warp  = threadIdx.x >> 5;
    const int lane  = threadIdx.x & 31;
    const int tok0  = blockIdx.x * 8 + (warp >> 1) * 4;
    const int rbase = (warp & 1) * 8;

    const float* xr = x + (size_t)tok0 * IN_CH + lane * 4;
    const float* Rp = Rm + (size_t)rbase * IN_CH + lane * 4;

    u64 acc[4][8];
#pragma unroll
    for (int t = 0; t < 4; t++)
#pragma unroll
        for (int r = 0; r < 8; r++) acc[t][r] = 0ull;

#pragma unroll 2
    for (int k = 0; k < IN_CH; k += 128) {
        // 4 token loads, streaming (x used exactly once chip-wide per row)
        uint4 xv0 = __ldcs(reinterpret_cast<const uint4*>(xr + 0 * IN_CH + k));
        uint4 xv1 = __ldcs(reinterpret_cast<const uint4*>(xr + 1 * IN_CH + k));
        uint4 xv2 = __ldcs(reinterpret_cast<const uint4*>(xr + 2 * IN_CH + k));
        uint4 xv3 = __ldcs(reinterpret_cast<const uint4*>(xr + 3 * IN_CH + k));
        const ulonglong2 x0 = *reinterpret_cast<const ulonglong2*>(&xv0);
        const ulonglong2 x1 = *reinterpret_cast<const ulonglong2*>(&xv1);
        const ulonglong2 x2 = *reinterpret_cast<const ulonglong2*>(&xv2);
        const ulonglong2 x3 = *reinterpret_cast<const ulonglong2*>(&xv3);
#pragma unroll
        for (int r = 0; r < 8; r++) {
            const ulonglong2 rv =
                *reinterpret_cast<const ulonglong2*>(Rp + (size_t)r * IN_CH + k);
            acc[0][r] = f2fma(x0.x, rv.x, acc[0][r]);
            acc[0][r] = f2fma(x0.y, rv.y, acc[0][r]);
            acc[1][r] = f2fma(x1.x, rv.x, acc[1][r]);
            acc[1][r] = f2fma(x1.y, rv.y, acc[1][r]);
            acc[2][r] = f2fma(x2.x, rv.x, acc[2][r]);
            acc[2][r] = f2fma(x2.y, rv.y, acc[2][r]);
            acc[3][r] = f2fma(x3.x, rv.x, acc[3][r]);
            acc[3][r] = f2fma(x3.y, rv.y, acc[3][r]);
        }
    }

    // cross-lane reduce; lane 0 writes the warp's 8-rank half of each t row
#pragma unroll
    for (int t = 0; t < 4; t++) {
        float s[8];
#pragma unroll
        for (int r = 0; r < 8; r++) {
            float2 v = *reinterpret_cast<float2*>(&acc[t][r]);
            s[r] = v.x + v.y;
        }
#pragma unroll
        for (int off = 16; off > 0; off >>= 1) {
#pragma unroll
            for (int r = 0; r < 8; r++)
                s[r] += __shfl_xor_sync(0xffffffffu, s[r], off);
        }
        if (lane == 0) {
            float4* o = reinterpret_cast<float4*>(
                g_t + (size_t)(tok0 + t) * RANK + rbase);
            o[0] = make_float4(s[0], s[1], s[2], s[3]);
            o[1] = make_float4(s[4], s[5], s[6], s[7]);
        }
    }
}

// ----------------------------------------------------------------------------
// Kernel 2: out[n, o] = bias[o] + sum_r t[n,r] * L[o,r]
// 128 thr x 4 outputs = 512-o chunk; 32 tokens/block -> grid 2048 (round-1
// geometry, best so far) + L transpose-packed in registers (32 u64) + t
// splatted in smem read as broadcast LDS.128. Plain STG.128 stores.
// ~98 regs -> 5 blocks/SM = 20 warps.
// ----------------------------------------------------------------------------
__global__ void __launch_bounds__(128)
k2_tLt(const float* __restrict__ Lm, const float* __restrict__ bias,
       float* __restrict__ out) {
    __shared__ __align__(16) u64 ts2[32][16];    // 4 KB splatted t

    const int tid     = threadIdx.x;
    const int bo      = blockIdx.x & 7;          // 8 o-chunks of 512
    const int bt      = blockIdx.x >> 3;         // 256 token tiles of 32
    const int tokbase = bt * 32;
    const int o4      = bo * 512 + tid * 4;

    // L[o4..o4+3][0..15] -> f32x2 packed regs
    u64 Lp0[16], Lp1[16];
    {
        float4 v[4][4];
#pragma unroll
        for (int i = 0; i < 4; i++) {
            const float4* lr = reinterpret_cast<const float4*>(Lm + (size_t)(o4 + i) * RANK);
            v[i][0] = lr[0]; v[i][1] = lr[1]; v[i][2] = lr[2]; v[i][3] = lr[3];
        }
#pragma unroll
        for (int q = 0; q < 4; q++) {
            Lp0[q * 4 + 0] = pack2(v[0][q].x, v[1][q].x);
            Lp0[q * 4 + 1] = pack2(v[0][q].y, v[1][q].y);
            Lp0[q * 4 + 2] = pack2(v[0][q].z, v[1][q].z);
            Lp0[q * 4 + 3] = pack2(v[0][q].w, v[1][q].w);
            Lp1[q * 4 + 0] = pack2(v[2][q].x, v[3][q].x);
            Lp1[q * 4 + 1] = pack2(v[2][q].y, v[3][q].y);
            Lp1[q * 4 + 2] = pack2(v[2][q].z, v[3][q].z);
            Lp1[q * 4 + 3] = pack2(v[2][q].w, v[3][q].w);
        }
    }
    const ulonglong2 bv = *reinterpret_cast<const ulonglong2*>(&bias[o4]);

    // stage splatted t: 32 tokens x 16 ranks; 4 threads per token
    {
        const int tok = tid >> 2;
        const int r0  = (tid & 3) * 4;
        float4 v = *reinterpret_cast<const float4*>(
            g_t + (size_t)(tokbase + tok) * RANK + r0);
        ts2[tok][r0 + 0] = splat2(v.x);
        ts2[tok][r0 + 1] = splat2(v.y);
        ts2[tok][r0 + 2] = splat2(v.z);
        ts2[tok][r0 + 3] = splat2(v.w);
    }
    __syncthreads();

    float* outp = out + (size_t)tokbase * OUT_CH + o4;
#pragma unroll 4
    for (int tok = 0; tok < 32; tok++) {
        const ulonglong2* tp2 = reinterpret_cast<const ulonglong2*>(ts2[tok]);
        u64 a0 = bv.x, a1 = bv.y;
#pragma unroll
        for (int h = 0; h < 8; h++) {
            ulonglong2 t2 = tp2[h];                 // broadcast LDS.128
            a0 = f2fma(t2.x, Lp0[h * 2 + 0], a0);
            a1 = f2fma(t2.x, Lp1[h * 2 + 0], a1);
            a0 = f2fma(t2.y, Lp0[h * 2 + 1], a0);
            a1 = f2fma(t2.y, Lp1[h * 2 + 1], a1);
        }
        ulonglong2 o;
        o.x = a0; o.y = a1;
        *reinterpret_cast<ulonglong2*>(outp + (size_t)tok * OUT_CH) = o;
    }
}

extern "C" void kernel_launch(void* const* d_in, const int* in_sizes, int n_in,
                              void* d_out, int out_size) {
    (void)in_sizes; (void)n_in; (void)out_size;
    const float* x    = (const float*)d_in[0];   // [8192, 4096]
    const float* Lm   = (const float*)d_in[1];   // [4096, 16]
    const float* Rm   = (const float*)d_in[2];   // [16, 4096]
    const float* bias = (const float*)d_in[3];   // [4096]
    float* out = (float*)d_out;                  // [8192, 4096]

    k1_xRt<<<N_TOKENS / 8, 128>>>(x, Rm);
    k2_tLt<<<(N_TOKENS / 32) * (OUT_CH / 512), 128>>>(Lm, bias, out);
}